// round 16
// baseline (speedup 1.0000x reference)
#include <cuda_runtime.h>
#include <cstdint>
#include <cstddef>

// ---------------- JAX threefry derivation (partitionable, VERIFIED R10) ------
// key(42)=(0,42); outer split -> K1=tf(key,0,0), K2=tf(key,0,1);
// _randint inner split -> lower key L = tf(K,0,1);
// bits[t] = o0^o1 of tf(L, 0, t); col = bits & 127.
// R10: PASS 88.5us. R15: PASS 79.7us (f4 k_means 20.1us + dbuf gemm0).
// R16 experiment: k_gemm0 -> tf32 mma.sync m16n8k8, 3xTF32 decomposition
// (hi*hi + hi*lo + lo*hi) for fp32-grade accuracy. k_means/k_layer1 unchanged.

static constexpr int F    = 256;   // feature dim
static constexpr int H2   = 256;   // 2*H concat dim
static constexpr int DEG  = 128;   // MAX_DEG
static constexpr int B    = 512;   // batch
static constexpr int S1n  = 25;
static constexpr int S2n  = 10;
static constexpr int NS1  = B * S2n;       // 5120 first-hop samples
static constexpr int MROWS = B + NS1;      // 5632 rows through layer 0

// scratch (static device allocation: allowed)
__device__ int   g_s1[NS1];
__device__ float g_xneigh[(size_t)MROWS * F];
__device__ float g_H[(size_t)MROWS * H2];

// ---------------- threefry2x32 (jax rotation schedule) ----------------
__device__ __forceinline__ uint32_t rotl32(uint32_t x, int r) {
    return (x << r) | (x >> (32 - r));
}

__device__ __forceinline__ void tf2x32(uint32_t k0, uint32_t k1,
                                       uint32_t x0, uint32_t x1,
                                       uint32_t& o0, uint32_t& o1) {
    uint32_t ks2 = k0 ^ k1 ^ 0x1BD11BDAu;
    x0 += k0; x1 += k1;
#define TFR(r) { x0 += x1; x1 = rotl32(x1, r); x1 ^= x0; }
    TFR(13) TFR(15) TFR(26) TFR(6)
    x0 += k1;  x1 += ks2 + 1u;
    TFR(17) TFR(29) TFR(16) TFR(24)
    x0 += ks2; x1 += k0 + 2u;
    TFR(13) TFR(15) TFR(26) TFR(6)
    x0 += k0;  x1 += k1 + 3u;
    TFR(17) TFR(29) TFR(16) TFR(24)
    x0 += k1;  x1 += ks2 + 4u;
    TFR(13) TFR(15) TFR(26) TFR(6)
    x0 += ks2; x1 += k0 + 5u;
#undef TFR
    o0 = x0; o1 = x1;
}

// Derive the two randint lower-bit keys L1 (hop-1) and L2 (hop-2).
__device__ __forceinline__ void get_lower_keys(uint32_t& l1a, uint32_t& l1b,
                                               uint32_t& l2a, uint32_t& l2b) {
    uint32_t k1a, k1b, k2a, k2b;
    tf2x32(0u, 42u, 0u, 0u, k1a, k1b);        // outer split child 0 -> hop-1 key
    tf2x32(0u, 42u, 0u, 1u, k2a, k2b);        // outer split child 1 -> hop-2 key
    tf2x32(k1a, k1b, 0u, 1u, l1a, l1b);       // randint inner split child 1
    tf2x32(k2a, k2b, 0u, 1u, l2a, l2b);
}

__device__ __forceinline__ uint32_t sample_col(uint32_t la, uint32_t lb,
                                               uint32_t t) {
    uint32_t o0, o1;
    tf2x32(la, lb, 0u, t, o0, o1);
    return (o0 ^ o1) & (DEG - 1u);
}

// first-hop sample t (0..NS1-1): adj[batch[t/10], c1(t)]
__device__ __forceinline__ int first_hop(const int* __restrict__ adj,
                                         const int* __restrict__ batch,
                                         uint32_t l1a, uint32_t l1b, int t) {
    uint32_t c = sample_col(l1a, l1b, (uint32_t)t);
    return adj[(size_t)batch[t / S2n] * DEG + c];
}

__device__ __forceinline__ float4 f4add(float4 a, float4 b) {
    return make_float4(a.x + b.x, a.y + b.y, a.z + b.z, a.w + b.w);
}

// ---------------- K2 v2: sampling + neighbor means (float4, 4 rows/block) ----
static constexpr int NB_SELF = B / 4;              // 128
static constexpr int NB_MEANS = NB_SELF + NS1 / 4; // 1408

__global__ __launch_bounds__(256) void k_means(const float* __restrict__ features,
                                               const int* __restrict__ adj,
                                               const int* __restrict__ batch) {
    __shared__ int nodes[4][S1n];
    __shared__ int sps[4];
    const int tid  = threadIdx.x;
    const int g    = tid >> 6;
    const int lane = tid & 63;
    const int blk  = blockIdx.x;

    uint32_t l1a, l1b, l2a, l2b;
    get_lower_keys(l1a, l1b, l2a, l2b);

    if (blk < NB_SELF) {
        const int b = blk * 4 + g;
        if (lane < S2n)
            nodes[g][lane] = first_hop(adj, batch, l1a, l1b, b * S2n + lane);
        __syncthreads();
        float4 s0 = make_float4(0.f, 0.f, 0.f, 0.f), s1 = s0;
#pragma unroll
        for (int j = 0; j < S2n; j += 2) {
            s0 = f4add(s0, *reinterpret_cast<const float4*>(
                               features + (size_t)nodes[g][j] * F + lane * 4));
            s1 = f4add(s1, *reinterpret_cast<const float4*>(
                               features + (size_t)nodes[g][j + 1] * F + lane * 4));
        }
        float4 r = f4add(s0, s1);
        const float inv = 1.f / (float)S2n;
        *reinterpret_cast<float4*>(g_xneigh + (size_t)b * F + lane * 4) =
            make_float4(r.x * inv, r.y * inv, r.z * inv, r.w * inv);
    } else {
        const int p = (blk - NB_SELF) * 4 + g;
        if (lane == 0) {
            int sp = first_hop(adj, batch, l1a, l1b, p);
            g_s1[p] = sp;           // consumed by K3 (next kernel)
            sps[g] = sp;
        }
        __syncthreads();
        if (lane < S1n) {
            uint32_t c = sample_col(l2a, l2b, (uint32_t)(p * S1n + lane));
            nodes[g][lane] = adj[(size_t)sps[g] * DEG + c];
        }
        __syncthreads();
        float4 s0 = make_float4(0.f, 0.f, 0.f, 0.f);
        float4 s1 = s0, s2 = s0, s3 = s0, s4 = s0;
#pragma unroll
        for (int j = 0; j < S1n; j += 5) {
            s0 = f4add(s0, *reinterpret_cast<const float4*>(
                               features + (size_t)nodes[g][j]     * F + lane * 4));
            s1 = f4add(s1, *reinterpret_cast<const float4*>(
                               features + (size_t)nodes[g][j + 1] * F + lane * 4));
            s2 = f4add(s2, *reinterpret_cast<const float4*>(
                               features + (size_t)nodes[g][j + 2] * F + lane * 4));
            s3 = f4add(s3, *reinterpret_cast<const float4*>(
                               features + (size_t)nodes[g][j + 3] * F + lane * 4));
            s4 = f4add(s4, *reinterpret_cast<const float4*>(
                               features + (size_t)nodes[g][j + 4] * F + lane * 4));
        }
        float4 r = f4add(f4add(f4add(s0, s1), f4add(s2, s3)), s4);
        const float inv = 1.f / (float)S1n;
        *reinterpret_cast<float4*>(g_xneigh + (size_t)(B + p) * F + lane * 4) =
            make_float4(r.x * inv, r.y * inv, r.z * inv, r.w * inv);
    }
}

// ---------------- K3 v3: layer-0 dual GEMM via tf32 mma.sync (3xTF32) -------
// H[r, 0:128]   = relu( X_self[r]  @ W_self_0 )
// H[r, 128:256] = relu( X_neigh[r] @ W_neigh_0 )
// Block tile 128(M) x 64(N), 8 warps in 4(M) x 2(N); warp tile 32x32 =
// m16n8k8 x (2 x 4). K-chunk 16, single smem buffer (hi+lo planes),
// register prefetch of next chunk issued before compute.
// 3xTF32: v = hi + lo (hi = cvt.rna.tf32); acc += Ah*Bh + Ah*Bl + Al*Bh.

__device__ __forceinline__ float tf32_hi(float v) {
    float r;
    asm("cvt.rna.tf32.f32 %0, %1;" : "=f"(r) : "f"(v));
    return r;
}

__device__ __forceinline__ void mma_tf32(float* d, const uint32_t* a,
                                         uint32_t b0, uint32_t b1) {
    asm volatile(
        "mma.sync.aligned.m16n8k8.row.col.f32.tf32.tf32.f32 "
        "{%0,%1,%2,%3}, {%4,%5,%6,%7}, {%8,%9}, {%0,%1,%2,%3};"
        : "+f"(d[0]), "+f"(d[1]), "+f"(d[2]), "+f"(d[3])
        : "r"(a[0]), "r"(a[1]), "r"(a[2]), "r"(a[3]), "r"(b0), "r"(b1));
}

__global__ __launch_bounds__(256) void k_gemm0(const float* __restrict__ features,
                                               const int* __restrict__ batch,
                                               const float* __restrict__ Ws0,
                                               const float* __restrict__ Wn0) {
    __shared__ float Ah[16][132], Al[16][132];   // k-major, padded
    __shared__ float Bh[16][68],  Bl[16][68];

    const int tid = threadIdx.x;
    const int r0  = blockIdx.x * 128;
    const int yb  = blockIdx.y;
    const bool selfhalf = (yb < 2);
    const int ncol0 = (yb & 1) * 64;
    const float* __restrict__ W = selfhalf ? Ws0 : Wn0;

    // staging map (same as v2): A rows tid>>2 and +64, k-quad tid&3
    const int rowA1 = tid >> 2;
    const int rowA2 = 64 + rowA1;
    const int kq    = tid & 3;
    const int bk = tid >> 4;           // 0..15
    const int bn = (tid & 15) * 4;     // 0..60

    const float* aptr1;
    const float* aptr2;
    {
        int ra = r0 + rowA1, rb = r0 + rowA2;
        if (selfhalf) {
            int na = (ra < B) ? batch[ra] : g_s1[ra - B];
            int nb = (rb < B) ? batch[rb] : g_s1[rb - B];
            aptr1 = features + (size_t)na * F;
            aptr2 = features + (size_t)nb * F;
        } else {
            aptr1 = g_xneigh + (size_t)ra * F;
            aptr2 = g_xneigh + (size_t)rb * F;
        }
    }

    // warp/fragment coordinates
    const int wid  = tid >> 5;
    const int lane = tid & 31;
    const int wm   = wid & 3;          // 0..3 -> 32-row slab
    const int wn   = wid >> 2;         // 0..1 -> 32-col slab
    const int tig  = lane & 3;         // thread-in-group
    const int grp  = lane >> 2;        // group id 0..7

    float acc[2][4][4];
#pragma unroll
    for (int mt = 0; mt < 2; mt++)
#pragma unroll
        for (int nt = 0; nt < 4; nt++)
#pragma unroll
            for (int i = 0; i < 4; i++) acc[mt][nt][i] = 0.f;

    float4 a1 = *reinterpret_cast<const float4*>(aptr1 + kq * 4);
    float4 a2 = *reinterpret_cast<const float4*>(aptr2 + kq * 4);
    float4 bv = *reinterpret_cast<const float4*>(W + (size_t)bk * 128 + ncol0 + bn);

    for (int c = 0; c < 16; c++) {
        __syncthreads();   // readers of previous chunk done
        {   // decompose + store chunk c
            float va[8] = {a1.x, a1.y, a1.z, a1.w, a2.x, a2.y, a2.z, a2.w};
#pragma unroll
            for (int i = 0; i < 4; i++) {
                float h1 = tf32_hi(va[i]);
                Ah[kq * 4 + i][rowA1] = h1;  Al[kq * 4 + i][rowA1] = va[i] - h1;
                float h2 = tf32_hi(va[4 + i]);
                Ah[kq * 4 + i][rowA2] = h2;  Al[kq * 4 + i][rowA2] = va[4 + i] - h2;
            }
            float vb[4] = {bv.x, bv.y, bv.z, bv.w};
#pragma unroll
            for (int i = 0; i < 4; i++) {
                float h = tf32_hi(vb[i]);
                Bh[bk][bn + i] = h;  Bl[bk][bn + i] = vb[i] - h;
            }
        }
        __syncthreads();   // chunk c visible
        if (c < 15) {      // prefetch chunk c+1 (latency hidden under MMAs)
            const int kk = (c + 1) * 16;
            a1 = *reinterpret_cast<const float4*>(aptr1 + kk + kq * 4);
            a2 = *reinterpret_cast<const float4*>(aptr2 + kk + kq * 4);
            bv = *reinterpret_cast<const float4*>(W + (size_t)(kk + bk) * 128 + ncol0 + bn);
        }
        // compute chunk c: two k=8 slices
#pragma unroll
        for (int s = 0; s < 2; s++) {
            const int kk = s * 8 + tig;
            uint32_t ah[2][4], al[2][4];
#pragma unroll
            for (int mt = 0; mt < 2; mt++) {
                const int m = wm * 32 + mt * 16 + grp;
                ah[mt][0] = __float_as_uint(Ah[kk][m]);
                ah[mt][1] = __float_as_uint(Ah[kk][m + 8]);
                ah[mt][2] = __float_as_uint(Ah[kk + 4][m]);
                ah[mt][3] = __float_as_uint(Ah[kk + 4][m + 8]);
                al[mt][0] = __float_as_uint(Al[kk][m]);
                al[mt][1] = __float_as_uint(Al[kk][m + 8]);
                al[mt][2] = __float_as_uint(Al[kk + 4][m]);
                al[mt][3] = __float_as_uint(Al[kk + 4][m + 8]);
            }
#pragma unroll
            for (int nt = 0; nt < 4; nt++) {
                const int n = wn * 32 + nt * 8 + grp;
                uint32_t bh0 = __float_as_uint(Bh[kk][n]);
                uint32_t bh1 = __float_as_uint(Bh[kk + 4][n]);
                uint32_t bl0 = __float_as_uint(Bl[kk][n]);
                uint32_t bl1 = __float_as_uint(Bl[kk + 4][n]);
#pragma unroll
                for (int mt = 0; mt < 2; mt++) {
                    mma_tf32(acc[mt][nt], ah[mt], bh0, bh1);
                    mma_tf32(acc[mt][nt], ah[mt], bl0, bl1);
                    mma_tf32(acc[mt][nt], al[mt], bh0, bh1);
                }
            }
        }
    }

    // epilogue: relu + store (D frag: rows grp/+8, cols 2*tig/+1)
    const int gcolbase = (selfhalf ? 0 : 128) + ncol0 + wn * 32;
#pragma unroll
    for (int mt = 0; mt < 2; mt++) {
        const int row = r0 + wm * 32 + mt * 16 + grp;
#pragma unroll
        for (int nt = 0; nt < 4; nt++) {
            const int col = gcolbase + nt * 8 + 2 * tig;
            float2 lo, hi;
            lo.x = fmaxf(acc[mt][nt][0], 0.f);
            lo.y = fmaxf(acc[mt][nt][1], 0.f);
            hi.x = fmaxf(acc[mt][nt][2], 0.f);
            hi.y = fmaxf(acc[mt][nt][3], 0.f);
            *reinterpret_cast<float2*>(&g_H[(size_t)row * H2 + col]) = lo;
            *reinterpret_cast<float2*>(&g_H[(size_t)(row + 8) * H2 + col]) = hi;
        }
    }
}

// ---------------- K4: layer-1 GEMM + l2 normalize ----------------
__global__ __launch_bounds__(256) void k_layer1(const float* __restrict__ Ws1,
                                                const float* __restrict__ Wn1,
                                                float* __restrict__ out) {
    __shared__ float xs[2][8][H2];   // [0]=self rows, [1]=neighbor means
    __shared__ float rowsq[8];
    const int tid = threadIdx.x;
    const int r0  = blockIdx.x * 8;

#pragma unroll
    for (int i = 0; i < 8; i++)
        xs[0][i][tid] = g_H[(size_t)(r0 + i) * H2 + tid];
#pragma unroll
    for (int i = 0; i < 8; i++) {
        float s0 = 0.f, s1 = 0.f;
#pragma unroll
        for (int j = 0; j < S2n; j += 2) {
            s0 += g_H[(size_t)(B + (r0 + i) * S2n + j)     * H2 + tid];
            s1 += g_H[(size_t)(B + (r0 + i) * S2n + j + 1) * H2 + tid];
        }
        xs[1][i][tid] = (s0 + s1) * (1.f / (float)S2n);
    }
    if (tid < 8) rowsq[tid] = 0.f;
    __syncthreads();

    const bool sp = (tid < 128);
    const float* __restrict__ W = sp ? (Ws1 + tid) : (Wn1 + (tid - 128));
    const float* X = sp ? &xs[0][0][0] : &xs[1][0][0];

    float acc[8] = {0.f, 0.f, 0.f, 0.f, 0.f, 0.f, 0.f, 0.f};
#pragma unroll 8
    for (int k = 0; k < H2; k++) {
        float wv = W[(size_t)k * 128];
#pragma unroll
        for (int i = 0; i < 8; i++)
            acc[i] += X[i * H2 + k] * wv;
    }

#pragma unroll
    for (int i = 0; i < 8; i++) {
        float v = acc[i] * acc[i];
#pragma unroll
        for (int o = 16; o > 0; o >>= 1)
            v += __shfl_down_sync(0xffffffffu, v, o);
        if ((tid & 31) == 0) atomicAdd(&rowsq[i], v);
    }
    __syncthreads();

#pragma unroll
    for (int i = 0; i < 8; i++) {
        float nrm = fmaxf(sqrtf(rowsq[i]), 1e-12f);
        out[(size_t)(r0 + i) * H2 + tid] = acc[i] / nrm;
    }
}

// ---------------- launch ----------------
extern "C" void kernel_launch(void* const* d_in, const int* in_sizes, int n_in,
                              void* d_out, int out_size) {
    const float* features = (const float*)d_in[0];
    const int*   adj      = (const int*)d_in[1];
    const int*   batch    = (const int*)d_in[2];
    const float* Ws0      = (const float*)d_in[3];
    const float* Wn0      = (const float*)d_in[4];
    const float* Ws1      = (const float*)d_in[5];
    const float* Wn1      = (const float*)d_in[6];
    float* out = (float*)d_out;

    k_means<<<NB_MEANS, 256>>>(features, adj, batch);
    k_gemm0<<<dim3(44, 4), 256>>>(features, batch, Ws0, Wn0);
    k_layer1<<<B / 8, 256>>>(Ws1, Wn1, out);
}